// round 16
// baseline (speedup 1.0000x reference)
#include <cuda_runtime.h>
#include <cuda_bf16.h>
#include <cuda_fp16.h>
#include <cstdint>
#include <math.h>

#define N_NODES   4000
#define N_LAYERS  8
#define PER_LAYER 500
#define IN_DEG    32
#define BATCH     2048
#define IN_DIM    784
#define OUT_DIM   10
#define EDGES_PER_LAYER (PER_LAYER * IN_DEG)

/* ---- GEMM config: CTA 64x64, 2x2 warps of 32x32, 3-term bf16, 4-stage ---- */
#define KP    832
#define KC    32
#define NKCH  (KP / KC)           /* 26 */
#define NPAD  512
#define RS    40
#define OFF_AH 0
#define OFF_AL (64 * RS)
#define OFF_BH (128 * RS)
#define OFF_BL (192 * RS)
#define ST    (256 * RS)
#define GEMM_STAGES 4
#define GEMM_SMEM_BYTES (GEMM_STAGES * ST * 2)   /* 81920 B */

/* ---- device scratch ---- */
__device__ __align__(16) __half g_hh[(size_t)N_NODES * BATCH];   /* fp16 activations */
__device__ __align__(16) __nv_bfloat16 g_xhi[(size_t)BATCH * KP];
__device__ __align__(16) __nv_bfloat16 g_xlo[(size_t)BATCH * KP];
__device__ __align__(16) __nv_bfloat16 g_whi[(size_t)NPAD * KP];
__device__ __align__(16) __nv_bfloat16 g_wlo[(size_t)NPAD * KP];

/* ================= asm helpers ================= */
__device__ __forceinline__ uint32_t smem_u32(const void* p) {
    uint32_t a;
    asm("{ .reg .u64 t; cvta.to.shared.u64 t, %1; cvt.u32.u64 %0, t; }"
        : "=r"(a) : "l"(p));
    return a;
}

#define CP16(dst, src) \
    asm volatile("cp.async.cg.shared.global [%0], [%1], 16;" \
                 :: "r"(dst), "l"(src))
#define CP_COMMIT() asm volatile("cp.async.commit_group;" ::: "memory")
#define CP_WAIT2()  asm volatile("cp.async.wait_group 2;"  ::: "memory")

#define LDSM4(R, addr) \
    asm volatile("ldmatrix.sync.aligned.m8n8.x4.shared.b16 {%0,%1,%2,%3}, [%4];" \
                 : "=r"((R)[0]), "=r"((R)[1]), "=r"((R)[2]), "=r"((R)[3]) \
                 : "r"(addr))

#define MMA_BF16(acc, a, b0, b1) \
    asm volatile("mma.sync.aligned.m16n8k16.row.col.f32.bf16.bf16.f32 " \
                 "{%0,%1,%2,%3}, {%4,%5,%6,%7}, {%8,%9}, {%0,%1,%2,%3};" \
                 : "+f"((acc)[0]), "+f"((acc)[1]), "+f"((acc)[2]), "+f"((acc)[3]) \
                 : "r"((a)[0]), "r"((a)[1]), "r"((a)[2]), "r"((a)[3]), \
                   "r"(b0), "r"(b1))

/* ======= Kernel 0: fused fp32 -> bf16 hi/lo split ======= */
__global__ __launch_bounds__(256) void split_kernel(
    const float* __restrict__ x, const float* __restrict__ W)
{
    int idx = blockIdx.x * 256 + threadIdx.x;
    if (idx < BATCH * KP) {
        int r = idx / KP, k = idx % KP;
        float v = (k < IN_DIM) ? x[(size_t)r * IN_DIM + k] : 0.f;
        __nv_bfloat16 hi = __float2bfloat16(v);
        g_xhi[idx] = hi;
        g_xlo[idx] = __float2bfloat16(v - __bfloat162float(hi));
    } else {
        int j = idx - BATCH * KP;
        if (j >= NPAD * KP) return;
        int r = j / KP, k = j % KP;
        float v = (r < PER_LAYER && k < IN_DIM) ? W[(size_t)r * IN_DIM + k] : 0.f;
        __nv_bfloat16 hi = __float2bfloat16(v);
        g_whi[j] = hi;
        g_wlo[j] = __float2bfloat16(v - __bfloat162float(hi));
    }
}

/* ======= Kernel 1: input GEMM (fp16 epilogue) ======= */
__global__ __launch_bounds__(128) void gemm_in_mma(const float* __restrict__ bias) {
    extern __shared__ __align__(16) __nv_bfloat16 sm[];
    const uint32_t smb = smem_u32(sm);

    const int tid  = threadIdx.x;
    const int lane = tid & 31, warp = tid >> 5;
    const int m0 = blockIdx.x * 64;
    const int n0 = blockIdx.y * 64;
    const int wm = (warp & 1) * 32;
    const int wn = (warp >> 1) * 32;

    const int g    = lane >> 2;
    const int tig  = lane & 3;
    const int quad = lane >> 3;
    const int qr   = lane & 7;
    const int a_off = ((quad & 1) * 8 + qr) * RS + (quad >> 1) * 8;
    const int b_off = ((quad >> 1) * 8 + qr) * RS + (quad & 1) * 8;

    float acc[2][4][4];
    #pragma unroll
    for (int i = 0; i < 2; i++)
        #pragma unroll
        for (int j = 0; j < 4; j++)
            #pragma unroll
            for (int q = 0; q < 4; q++) acc[i][j][q] = 0.f;

    auto issue = [&](int c, int s) {
        const int k0 = c * KC;
        const uint32_t base = smb + (uint32_t)(s * ST) * 2;
        #pragma unroll
        for (int i = 0; i < 8; i++) {
            const int idx   = tid + i * 128;
            const int chunk = idx & 3;
            const int row   = (idx >> 2) & 63;
            const int tile  = idx >> 8;
            const __nv_bfloat16* src;
            switch (tile) {
                case 0:  src = &g_xhi[(size_t)(m0 + row) * KP]; break;
                case 1:  src = &g_xlo[(size_t)(m0 + row) * KP]; break;
                case 2:  src = &g_whi[(size_t)(n0 + row) * KP]; break;
                default: src = &g_wlo[(size_t)(n0 + row) * KP]; break;
            }
            CP16(base + (uint32_t)(tile * 64 * RS + row * RS + chunk * 8) * 2,
                 src + k0 + chunk * 8);
        }
    };

    issue(0, 0); CP_COMMIT();
    issue(1, 1); CP_COMMIT();
    issue(2, 2); CP_COMMIT();

    for (int c = 0; c < NKCH; c++) {
        const int s = c & (GEMM_STAGES - 1);
        CP_WAIT2();
        __syncthreads();

        const uint32_t base = smb + (uint32_t)(s * ST) * 2;
        #pragma unroll
        for (int ks = 0; ks < KC; ks += 16) {
            uint32_t ah[2][4], al[2][4], bh[2][4], bl[2][4];
            #pragma unroll
            for (int mi = 0; mi < 2; mi++) {
                const uint32_t ao = base + (uint32_t)((wm + mi * 16) * RS + ks + a_off) * 2;
                LDSM4(ah[mi], ao + OFF_AH * 2);
                LDSM4(al[mi], ao + OFF_AL * 2);
            }
            #pragma unroll
            for (int njp = 0; njp < 2; njp++) {
                const uint32_t bo = base + (uint32_t)((wn + njp * 16) * RS + ks + b_off) * 2;
                LDSM4(bh[njp], bo + OFF_BH * 2);
                LDSM4(bl[njp], bo + OFF_BL * 2);
            }
            #pragma unroll
            for (int mi = 0; mi < 2; mi++) {
                #pragma unroll
                for (int njp = 0; njp < 2; njp++) {
                    #pragma unroll
                    for (int sub = 0; sub < 2; sub++) {
                        float* a4 = acc[mi][njp * 2 + sub];
                        MMA_BF16(a4, ah[mi], bh[njp][sub * 2], bh[njp][sub * 2 + 1]);
                        MMA_BF16(a4, al[mi], bh[njp][sub * 2], bh[njp][sub * 2 + 1]);
                        MMA_BF16(a4, ah[mi], bl[njp][sub * 2], bl[njp][sub * 2 + 1]);
                    }
                }
            }
        }
        __syncthreads();
        if (c + 3 < NKCH) issue(c + 3, (c + 3) & (GEMM_STAGES - 1));
        CP_COMMIT();
    }

    /* epilogue -> g_hh (fp16), relu(acc + bias) */
    #pragma unroll
    for (int mi = 0; mi < 2; mi++) {
        const int m = m0 + wm + mi * 16 + g;
        #pragma unroll
        for (int nj = 0; nj < 4; nj++) {
            const int n = n0 + wn + nj * 8 + 2 * tig;
            if (n < PER_LAYER) {
                const float b0 = __ldg(&bias[n]);
                const float b1 = __ldg(&bias[n + 1]);
                float* a4 = acc[mi][nj];
                g_hh[(size_t)n * BATCH + m]           = __float2half_rn(fmaxf(a4[0] + b0, 0.f));
                g_hh[(size_t)(n + 1) * BATCH + m]     = __float2half_rn(fmaxf(a4[1] + b1, 0.f));
                g_hh[(size_t)n * BATCH + m + 8]       = __float2half_rn(fmaxf(a4[2] + b0, 0.f));
                g_hh[(size_t)(n + 1) * BATCH + m + 8] = __float2half_rn(fmaxf(a4[3] + b1, 0.f));
            }
        }
    }
}

/* ======= Kernel 2: DAG layer — 64 thr x 2000 CTAs, unroll 16 =======
   Same geometry/body as measured-best; deeper unroll doubles loads in
   flight (MLP 8 -> 16) to attack the measured 5x latency exposure.   */
__global__ __launch_bounds__(64) void spmm_layer_kernel(
    const float* __restrict__ w_edge,
    const int*   __restrict__ edge_src,
    const int layer)
{
    const int v = blockIdx.y;
    const int c = (blockIdx.x * 64 + threadIdx.x) * 8;
    const int base = (layer - 1) * EDGES_PER_LAYER + v * IN_DEG;

    __shared__ int   s_src[IN_DEG];
    __shared__ float s_w[IN_DEG];
    if (threadIdx.x < IN_DEG) {
        s_src[threadIdx.x] = edge_src[base + threadIdx.x];
        s_w[threadIdx.x]   = w_edge[base + threadIdx.x];
    }
    __syncthreads();

    float a0 = 0.f, a1 = 0.f, a2 = 0.f, a3 = 0.f;
    float a4 = 0.f, a5 = 0.f, a6 = 0.f, a7 = 0.f;

    #pragma unroll 16
    for (int e = 0; e < IN_DEG; e++) {
        const float w = s_w[e];
        const uint4 hv = *reinterpret_cast<const uint4*>(
            &g_hh[(size_t)s_src[e] * BATCH + c]);
        const float2 f0 = __half22float2(*reinterpret_cast<const __half2*>(&hv.x));
        const float2 f1 = __half22float2(*reinterpret_cast<const __half2*>(&hv.y));
        const float2 f2 = __half22float2(*reinterpret_cast<const __half2*>(&hv.z));
        const float2 f3 = __half22float2(*reinterpret_cast<const __half2*>(&hv.w));
        a0 += w * f0.x; a1 += w * f0.y;
        a2 += w * f1.x; a3 += w * f1.y;
        a4 += w * f2.x; a5 += w * f2.y;
        a6 += w * f3.x; a7 += w * f3.y;
    }

    const int dst = layer * PER_LAYER + v;
    const __half2 r0 = __floats2half2_rn(fmaxf(a0, 0.f), fmaxf(a1, 0.f));
    const __half2 r1 = __floats2half2_rn(fmaxf(a2, 0.f), fmaxf(a3, 0.f));
    const __half2 r2 = __floats2half2_rn(fmaxf(a4, 0.f), fmaxf(a5, 0.f));
    const __half2 r3 = __floats2half2_rn(fmaxf(a6, 0.f), fmaxf(a7, 0.f));
    uint4 st;
    st.x = *reinterpret_cast<const uint32_t*>(&r0);
    st.y = *reinterpret_cast<const uint32_t*>(&r1);
    st.z = *reinterpret_cast<const uint32_t*>(&r2);
    st.w = *reinterpret_cast<const uint32_t*>(&r3);
    *reinterpret_cast<uint4*>(&g_hh[(size_t)dst * BATCH + c]) = st;
}

/* ======= Kernel 3: fused output projection (single pass) =======
   thread t = o*BATCH + b -> hv loads coalesced in b; W_out/verts
   uniform per warp. One launch, no partial buffer.               */
__global__ __launch_bounds__(256) void out_kernel(
    const float* __restrict__ W_out,
    const int*   __restrict__ out_verts,
    const float* __restrict__ b_out,
    float* __restrict__ out,
    const int v_out)
{
    const int t = blockIdx.x * 256 + threadIdx.x;
    if (t >= OUT_DIM * BATCH) return;
    const int o = t >> 11;           /* / BATCH */
    const int b = t & 2047;

    float s = __ldg(&b_out[o]);
    const float* Wrow = &W_out[(size_t)o * v_out];

    #pragma unroll 4
    for (int v = 0; v < v_out; v++) {
        const int vert = __ldg(&out_verts[v]);
        s += __half2float(g_hh[(size_t)vert * BATCH + b]) * __ldg(&Wrow[v]);
    }
    out[b * OUT_DIM + o] = s;
}

/* ======= launcher ======= */
extern "C" void kernel_launch(void* const* d_in, const int* in_sizes, int n_in,
                              void* d_out, int out_size)
{
    const float* x        = (const float*)d_in[0];
    const float* W_in     = (const float*)d_in[1];
    const float* b_in     = (const float*)d_in[2];
    const float* w_edge   = (const float*)d_in[3];
    const float* W_out    = (const float*)d_in[4];
    const float* b_out    = (const float*)d_in[5];
    const int*   edge_src = (const int*)d_in[6];
    const int*   out_verts = (const int*)d_in[n_in - 1];
    const int    v_out     = in_sizes[n_in - 1];
    float* out = (float*)d_out;
    (void)out_size;

    cudaFuncSetAttribute(gemm_in_mma,
                         cudaFuncAttributeMaxDynamicSharedMemorySize,
                         GEMM_SMEM_BYTES);

    /* 0) fused split */
    {
        const int tot = BATCH * KP + NPAD * KP;
        split_kernel<<<(tot + 255) / 256, 256>>>(x, W_in);
    }

    /* 1) input GEMM */
    gemm_in_mma<<<dim3(BATCH / 64, NPAD / 64), 128, GEMM_SMEM_BYTES>>>(b_in);

    /* 2) 7 sequential sparse layers: 2000 CTAs x 64 thr, 8 elems/thread */
    for (int l = 1; l < N_LAYERS; l++) {
        dim3 grid(BATCH / (64 * 8), PER_LAYER);
        spmm_layer_kernel<<<grid, 64>>>(w_edge, edge_src, l);
    }

    /* 3) fused output projection (one launch) */
    out_kernel<<<(OUT_DIM * BATCH + 255) / 256, 256>>>(
        W_out, out_verts, b_out, out, v_out);
}

// round 17
// speedup vs baseline: 1.3329x; 1.3329x over previous
#include <cuda_runtime.h>
#include <cuda_bf16.h>
#include <cuda_fp16.h>
#include <cstdint>
#include <math.h>

#define N_NODES   4000
#define N_LAYERS  8
#define PER_LAYER 500
#define IN_DEG    32
#define BATCH     2048
#define IN_DIM    784
#define OUT_DIM   10
#define EDGES_PER_LAYER (PER_LAYER * IN_DEG)
#define NCHUNKS_OUT 8

/* ---- GEMM config: CTA 64x64, 2x2 warps of 32x32, 3-term bf16, 4-stage ---- */
#define KP    832
#define KC    32
#define NKCH  (KP / KC)           /* 26 */
#define NPAD  512
#define RS    40
#define OFF_AH 0
#define OFF_AL (64 * RS)
#define OFF_BH (128 * RS)
#define OFF_BL (192 * RS)
#define ST    (256 * RS)
#define GEMM_STAGES 4
#define GEMM_SMEM_BYTES (GEMM_STAGES * ST * 2)   /* 81920 B */

/* ---- device scratch ---- */
__device__ __align__(16) __half g_hh[(size_t)N_NODES * BATCH];   /* fp16 activations */
__device__ __align__(16) float g_part[NCHUNKS_OUT * BATCH * OUT_DIM];
__device__ __align__(16) __nv_bfloat16 g_xhi[(size_t)BATCH * KP];
__device__ __align__(16) __nv_bfloat16 g_xlo[(size_t)BATCH * KP];
__device__ __align__(16) __nv_bfloat16 g_whi[(size_t)NPAD * KP];
__device__ __align__(16) __nv_bfloat16 g_wlo[(size_t)NPAD * KP];

/* ================= asm helpers ================= */
__device__ __forceinline__ uint32_t smem_u32(const void* p) {
    uint32_t a;
    asm("{ .reg .u64 t; cvta.to.shared.u64 t, %1; cvt.u32.u64 %0, t; }"
        : "=r"(a) : "l"(p));
    return a;
}

#define CP16(dst, src) \
    asm volatile("cp.async.cg.shared.global [%0], [%1], 16;" \
                 :: "r"(dst), "l"(src))
#define CP_COMMIT() asm volatile("cp.async.commit_group;" ::: "memory")
#define CP_WAIT2()  asm volatile("cp.async.wait_group 2;"  ::: "memory")

#define LDSM4(R, addr) \
    asm volatile("ldmatrix.sync.aligned.m8n8.x4.shared.b16 {%0,%1,%2,%3}, [%4];" \
                 : "=r"((R)[0]), "=r"((R)[1]), "=r"((R)[2]), "=r"((R)[3]) \
                 : "r"(addr))

#define MMA_BF16(acc, a, b0, b1) \
    asm volatile("mma.sync.aligned.m16n8k16.row.col.f32.bf16.bf16.f32 " \
                 "{%0,%1,%2,%3}, {%4,%5,%6,%7}, {%8,%9}, {%0,%1,%2,%3};" \
                 : "+f"((acc)[0]), "+f"((acc)[1]), "+f"((acc)[2]), "+f"((acc)[3]) \
                 : "r"((a)[0]), "r"((a)[1]), "r"((a)[2]), "r"((a)[3]), \
                   "r"(b0), "r"(b1))

/* ======= Kernel 0: fused fp32 -> bf16 hi/lo split ======= */
__global__ __launch_bounds__(256) void split_kernel(
    const float* __restrict__ x, const float* __restrict__ W)
{
    int idx = blockIdx.x * 256 + threadIdx.x;
    if (idx < BATCH * KP) {
        int r = idx / KP, k = idx % KP;
        float v = (k < IN_DIM) ? x[(size_t)r * IN_DIM + k] : 0.f;
        __nv_bfloat16 hi = __float2bfloat16(v);
        g_xhi[idx] = hi;
        g_xlo[idx] = __float2bfloat16(v - __bfloat162float(hi));
    } else {
        int j = idx - BATCH * KP;
        if (j >= NPAD * KP) return;
        int r = j / KP, k = j % KP;
        float v = (r < PER_LAYER && k < IN_DIM) ? W[(size_t)r * IN_DIM + k] : 0.f;
        __nv_bfloat16 hi = __float2bfloat16(v);
        g_whi[j] = hi;
        g_wlo[j] = __float2bfloat16(v - __bfloat162float(hi));
    }
}

/* ======= Kernel 1: input GEMM (fp16 epilogue) ======= */
__global__ __launch_bounds__(128) void gemm_in_mma(const float* __restrict__ bias) {
    extern __shared__ __align__(16) __nv_bfloat16 sm[];
    const uint32_t smb = smem_u32(sm);

    const int tid  = threadIdx.x;
    const int lane = tid & 31, warp = tid >> 5;
    const int m0 = blockIdx.x * 64;
    const int n0 = blockIdx.y * 64;
    const int wm = (warp & 1) * 32;
    const int wn = (warp >> 1) * 32;

    const int g    = lane >> 2;
    const int tig  = lane & 3;
    const int quad = lane >> 3;
    const int qr   = lane & 7;
    const int a_off = ((quad & 1) * 8 + qr) * RS + (quad >> 1) * 8;
    const int b_off = ((quad >> 1) * 8 + qr) * RS + (quad & 1) * 8;

    float acc[2][4][4];
    #pragma unroll
    for (int i = 0; i < 2; i++)
        #pragma unroll
        for (int j = 0; j < 4; j++)
            #pragma unroll
            for (int q = 0; q < 4; q++) acc[i][j][q] = 0.f;

    auto issue = [&](int c, int s) {
        const int k0 = c * KC;
        const uint32_t base = smb + (uint32_t)(s * ST) * 2;
        #pragma unroll
        for (int i = 0; i < 8; i++) {
            const int idx   = tid + i * 128;
            const int chunk = idx & 3;
            const int row   = (idx >> 2) & 63;
            const int tile  = idx >> 8;
            const __nv_bfloat16* src;
            switch (tile) {
                case 0:  src = &g_xhi[(size_t)(m0 + row) * KP]; break;
                case 1:  src = &g_xlo[(size_t)(m0 + row) * KP]; break;
                case 2:  src = &g_whi[(size_t)(n0 + row) * KP]; break;
                default: src = &g_wlo[(size_t)(n0 + row) * KP]; break;
            }
            CP16(base + (uint32_t)(tile * 64 * RS + row * RS + chunk * 8) * 2,
                 src + k0 + chunk * 8);
        }
    };

    issue(0, 0); CP_COMMIT();
    issue(1, 1); CP_COMMIT();
    issue(2, 2); CP_COMMIT();

    for (int c = 0; c < NKCH; c++) {
        const int s = c & (GEMM_STAGES - 1);
        CP_WAIT2();
        __syncthreads();

        const uint32_t base = smb + (uint32_t)(s * ST) * 2;
        #pragma unroll
        for (int ks = 0; ks < KC; ks += 16) {
            uint32_t ah[2][4], al[2][4], bh[2][4], bl[2][4];
            #pragma unroll
            for (int mi = 0; mi < 2; mi++) {
                const uint32_t ao = base + (uint32_t)((wm + mi * 16) * RS + ks + a_off) * 2;
                LDSM4(ah[mi], ao + OFF_AH * 2);
                LDSM4(al[mi], ao + OFF_AL * 2);
            }
            #pragma unroll
            for (int njp = 0; njp < 2; njp++) {
                const uint32_t bo = base + (uint32_t)((wn + njp * 16) * RS + ks + b_off) * 2;
                LDSM4(bh[njp], bo + OFF_BH * 2);
                LDSM4(bl[njp], bo + OFF_BL * 2);
            }
            #pragma unroll
            for (int mi = 0; mi < 2; mi++) {
                #pragma unroll
                for (int njp = 0; njp < 2; njp++) {
                    #pragma unroll
                    for (int sub = 0; sub < 2; sub++) {
                        float* a4 = acc[mi][njp * 2 + sub];
                        MMA_BF16(a4, ah[mi], bh[njp][sub * 2], bh[njp][sub * 2 + 1]);
                        MMA_BF16(a4, al[mi], bh[njp][sub * 2], bh[njp][sub * 2 + 1]);
                        MMA_BF16(a4, ah[mi], bl[njp][sub * 2], bl[njp][sub * 2 + 1]);
                    }
                }
            }
        }
        __syncthreads();
        if (c + 3 < NKCH) issue(c + 3, (c + 3) & (GEMM_STAGES - 1));
        CP_COMMIT();
    }

    /* epilogue -> g_hh (fp16), relu(acc + bias) */
    #pragma unroll
    for (int mi = 0; mi < 2; mi++) {
        const int m = m0 + wm + mi * 16 + g;
        #pragma unroll
        for (int nj = 0; nj < 4; nj++) {
            const int n = n0 + wn + nj * 8 + 2 * tig;
            if (n < PER_LAYER) {
                const float b0 = __ldg(&bias[n]);
                const float b1 = __ldg(&bias[n + 1]);
                float* a4 = acc[mi][nj];
                g_hh[(size_t)n * BATCH + m]           = __float2half_rn(fmaxf(a4[0] + b0, 0.f));
                g_hh[(size_t)(n + 1) * BATCH + m]     = __float2half_rn(fmaxf(a4[1] + b1, 0.f));
                g_hh[(size_t)n * BATCH + m + 8]       = __float2half_rn(fmaxf(a4[2] + b0, 0.f));
                g_hh[(size_t)(n + 1) * BATCH + m + 8] = __float2half_rn(fmaxf(a4[3] + b1, 0.f));
            }
        }
    }
}

/* ======= Kernel 2: DAG layer — 64 thr x 2000 CTAs, unroll 16 =======
   Measured-best: 9.18 us/layer (R16 profile).                        */
__global__ __launch_bounds__(64) void spmm_layer_kernel(
    const float* __restrict__ w_edge,
    const int*   __restrict__ edge_src,
    const int layer)
{
    const int v = blockIdx.y;
    const int c = (blockIdx.x * 64 + threadIdx.x) * 8;
    const int base = (layer - 1) * EDGES_PER_LAYER + v * IN_DEG;

    __shared__ int   s_src[IN_DEG];
    __shared__ float s_w[IN_DEG];
    if (threadIdx.x < IN_DEG) {
        s_src[threadIdx.x] = edge_src[base + threadIdx.x];
        s_w[threadIdx.x]   = w_edge[base + threadIdx.x];
    }
    __syncthreads();

    float a0 = 0.f, a1 = 0.f, a2 = 0.f, a3 = 0.f;
    float a4 = 0.f, a5 = 0.f, a6 = 0.f, a7 = 0.f;

    #pragma unroll 16
    for (int e = 0; e < IN_DEG; e++) {
        const float w = s_w[e];
        const uint4 hv = *reinterpret_cast<const uint4*>(
            &g_hh[(size_t)s_src[e] * BATCH + c]);
        const float2 f0 = __half22float2(*reinterpret_cast<const __half2*>(&hv.x));
        const float2 f1 = __half22float2(*reinterpret_cast<const __half2*>(&hv.y));
        const float2 f2 = __half22float2(*reinterpret_cast<const __half2*>(&hv.z));
        const float2 f3 = __half22float2(*reinterpret_cast<const __half2*>(&hv.w));
        a0 += w * f0.x; a1 += w * f0.y;
        a2 += w * f1.x; a3 += w * f1.y;
        a4 += w * f2.x; a5 += w * f2.y;
        a6 += w * f3.x; a7 += w * f3.y;
    }

    const int dst = layer * PER_LAYER + v;
    const __half2 r0 = __floats2half2_rn(fmaxf(a0, 0.f), fmaxf(a1, 0.f));
    const __half2 r1 = __floats2half2_rn(fmaxf(a2, 0.f), fmaxf(a3, 0.f));
    const __half2 r2 = __floats2half2_rn(fmaxf(a4, 0.f), fmaxf(a5, 0.f));
    const __half2 r3 = __floats2half2_rn(fmaxf(a6, 0.f), fmaxf(a7, 0.f));
    uint4 st;
    st.x = *reinterpret_cast<const uint32_t*>(&r0);
    st.y = *reinterpret_cast<const uint32_t*>(&r1);
    st.z = *reinterpret_cast<const uint32_t*>(&r2);
    st.w = *reinterpret_cast<const uint32_t*>(&r3);
    *reinterpret_cast<uint4*>(&g_hh[(size_t)dst * BATCH + c]) = st;
}

/* ======= Kernel 3a/3b: output projection (measured R15 config) ======= */
__global__ __launch_bounds__(256) void out_partial_kernel(
    const float* __restrict__ W_out,
    const int*   __restrict__ out_verts,
    const int v_out)
{
    const int b = blockIdx.x * blockDim.x + threadIdx.x;
    const int chunk = blockIdx.y;
    const int csz = (v_out + NCHUNKS_OUT - 1) / NCHUNKS_OUT;
    const int v0 = chunk * csz;
    const int v1 = (v0 + csz < v_out) ? (v0 + csz) : v_out;

    float acc[OUT_DIM];
    #pragma unroll
    for (int o = 0; o < OUT_DIM; o++) acc[o] = 0.f;

    for (int v = v0; v < v1; v++) {
        const int vert = __ldg(&out_verts[v]);
        const float hv = __half2float(g_hh[(size_t)vert * BATCH + b]);
        #pragma unroll
        for (int o = 0; o < OUT_DIM; o++)
            acc[o] += hv * __ldg(&W_out[(size_t)o * v_out + v]);
    }
    float* p = &g_part[((size_t)chunk * BATCH + b) * OUT_DIM];
    #pragma unroll
    for (int o = 0; o < OUT_DIM; o++) p[o] = acc[o];
}

__global__ __launch_bounds__(256) void out_final_kernel(
    const float* __restrict__ b_out,
    float* __restrict__ out)
{
    const int idx = blockIdx.x * blockDim.x + threadIdx.x;
    if (idx < BATCH * OUT_DIM) {
        const int o = idx % OUT_DIM;
        float s = b_out[o];
        #pragma unroll
        for (int ch = 0; ch < NCHUNKS_OUT; ch++)
            s += g_part[(size_t)ch * BATCH * OUT_DIM + idx];
        out[idx] = s;
    }
}

/* ======= launcher ======= */
extern "C" void kernel_launch(void* const* d_in, const int* in_sizes, int n_in,
                              void* d_out, int out_size)
{
    const float* x        = (const float*)d_in[0];
    const float* W_in     = (const float*)d_in[1];
    const float* b_in     = (const float*)d_in[2];
    const float* w_edge   = (const float*)d_in[3];
    const float* W_out    = (const float*)d_in[4];
    const float* b_out    = (const float*)d_in[5];
    const int*   edge_src = (const int*)d_in[6];
    const int*   out_verts = (const int*)d_in[n_in - 1];
    const int    v_out     = in_sizes[n_in - 1];
    float* out = (float*)d_out;
    (void)out_size;

    cudaFuncSetAttribute(gemm_in_mma,
                         cudaFuncAttributeMaxDynamicSharedMemorySize,
                         GEMM_SMEM_BYTES);

    /* 0) fused split */
    {
        const int tot = BATCH * KP + NPAD * KP;
        split_kernel<<<(tot + 255) / 256, 256>>>(x, W_in);
    }

    /* 1) input GEMM */
    gemm_in_mma<<<dim3(BATCH / 64, NPAD / 64), 128, GEMM_SMEM_BYTES>>>(b_in);

    /* 2) 7 sequential sparse layers: 2000 CTAs x 64 thr, 8 elems/thread */
    for (int l = 1; l < N_LAYERS; l++) {
        dim3 grid(BATCH / (64 * 8), PER_LAYER);
        spmm_layer_kernel<<<grid, 64>>>(w_edge, edge_src, l);
    }

    /* 3) output projection (chunk-parallel two-kernel, measured ~4 us) */
    {
        dim3 grid(BATCH / 256, NCHUNKS_OUT);
        out_partial_kernel<<<grid, 256>>>(W_out, out_verts, v_out);
        out_final_kernel<<<(BATCH * OUT_DIM + 255) / 256, 256>>>(b_out, out);
    }
}